// round 8
// baseline (speedup 1.0000x reference)
#include <cuda_runtime.h>

#define BATCH 1024
#define FEAT 256
#define NUM_CLASSES 100000
#define CLAMP_MIN 1e-12f
#define CLAMP_MAX 1e12f
#define WARPS_PER_BLOCK 8
#define ROWS_PER_WARP 2
#define ROWS_PER_BLOCK (WARPS_PER_BLOCK * ROWS_PER_WARP)   // 16
#define NUM_BLOCKS (BATCH / ROWS_PER_BLOCK)                // 64

// Packed cross-block accumulator:
//   bits [52:64) = arrived-block count, bits [0:52) = sum in 2^-20 fixed point.
// One relaxed u64 RMW carries both the data and the "am I last?" ticket ->
// no fence, no second atomic, no final load. Quantization: <=2^-21 per block
// (64 blocks) -> ~1e-10 relative on a loss of ~512.
#define COUNT_ONE (1ULL << 52)
#define SUM_MASK  (COUNT_ONE - 1ULL)
#define FIX_SCALE 1048576.0   // 2^20

__device__ unsigned long long g_pack = 0ULL;   // zero at load; reset by last block

__global__ __launch_bounds__(WARPS_PER_BLOCK * 32)
void center_loss_kernel(const float* __restrict__ x,
                        const float* __restrict__ centers,
                        const int* __restrict__ labels,   // JAX x64 disabled -> int32
                        float* __restrict__ out) {
    const int warp = threadIdx.x >> 5;
    const int lane = threadIdx.x & 31;
    const int row0 = (blockIdx.x * WARPS_PER_BLOCK + warp) * ROWS_PER_WARP;

    // Both label loads issue immediately; start the two gather chains early.
    int l0 = __ldg(&labels[row0]);
    int l1 = __ldg(&labels[row0 + 1]);
    l0 = min(max(l0, 0), NUM_CLASSES - 1);
    l1 = min(max(l1, 0), NUM_CLASSES - 1);

    const float4* xr0 = reinterpret_cast<const float4*>(x + (size_t)row0 * FEAT);
    const float4* xr1 = reinterpret_cast<const float4*>(x + (size_t)(row0 + 1) * FEAT);
    const float4* cr0 = reinterpret_cast<const float4*>(centers + (size_t)l0 * FEAT);
    const float4* cr1 = reinterpret_cast<const float4*>(centers + (size_t)l1 * FEAT);

    // 8 independent 16B loads per lane -> deep MLP while chains resolve.
    float4 a0 = xr0[lane], a1 = xr0[lane + 32];
    float4 a2 = xr1[lane], a3 = xr1[lane + 32];
    float4 b0 = cr0[lane], b1 = cr0[lane + 32];
    float4 b2 = cr1[lane], b3 = cr1[lane + 32];

    // Per-lane partial of ||x||^2 + ||c||^2 - 2 x.c == ||x-c||^2, per row.
    float d0, d1;
    {
        float t;
        t = a0.x - b0.x; d0  = t * t;  t = a0.y - b0.y; d0 += t * t;
        t = a0.z - b0.z; d0 += t * t;  t = a0.w - b0.w; d0 += t * t;
        t = a1.x - b1.x; d0 += t * t;  t = a1.y - b1.y; d0 += t * t;
        t = a1.z - b1.z; d0 += t * t;  t = a1.w - b1.w; d0 += t * t;
        t = a2.x - b2.x; d1  = t * t;  t = a2.y - b2.y; d1 += t * t;
        t = a2.z - b2.z; d1 += t * t;  t = a2.w - b2.w; d1 += t * t;
        t = a3.x - b3.x; d1 += t * t;  t = a3.y - b3.y; d1 += t * t;
        t = a3.z - b3.z; d1 += t * t;  t = a3.w - b3.w; d1 += t * t;
    }
    // Note: (x-c)^2 expanded == x^2 + c^2 - 2xc exactly in the reference's
    // real-number semantics; fp orderings differ at ~1e-7 rel, well in tol.

    // Two independent warp reductions; chains interleave in the scheduler.
    #pragma unroll
    for (int off = 16; off > 0; off >>= 1) {
        d0 += __shfl_xor_sync(0xFFFFFFFFu, d0, off);
        d1 += __shfl_xor_sync(0xFFFFFFFFu, d1, off);
    }

    __shared__ float bs[WARPS_PER_BLOCK];
    if (lane == 0) {
        // clamp is per ROW, before summing.
        bs[warp] = fminf(fmaxf(d0, CLAMP_MIN), CLAMP_MAX)
                 + fminf(fmaxf(d1, CLAMP_MIN), CLAMP_MAX);
    }
    __syncthreads();

    if (warp == 0 && lane < WARPS_PER_BLOCK) {
        float s = bs[lane];
        #pragma unroll
        for (int off = WARPS_PER_BLOCK / 2; off > 0; off >>= 1)
            s += __shfl_xor_sync((1u << WARPS_PER_BLOCK) - 1u, s, off);

        if (lane == 0) {
            unsigned long long val =
                COUNT_ONE + (unsigned long long)__double2ll_rn((double)s * FIX_SCALE);
            unsigned long long old = atomicAdd(&g_pack, val);

            if ((old >> 52) == NUM_BLOCKS - 1) {
                unsigned long long sum_fix = (old + val) & SUM_MASK;
                double tot = (double)sum_fix * (1.0 / FIX_SCALE);
                *out = (float)(tot * (1.0 / BATCH)
                             + (double)(NUM_CLASSES - 1) * 1e-12);
                g_pack = 0ULL;   // re-arm for next graph replay
            }
        }
    }
}

extern "C" void kernel_launch(void* const* d_in, const int* in_sizes, int n_in,
                              void* d_out, int out_size) {
    // Resolve inputs by element count:
    //   x: 1024*256 = 262144, centers: 100000*256 = 25600000, labels: 1024
    const float* x = nullptr;
    const float* centers = nullptr;
    const int*   labels = nullptr;
    for (int i = 0; i < n_in; i++) {
        if (in_sizes[i] == BATCH * FEAT)            x       = (const float*)d_in[i];
        else if (in_sizes[i] == NUM_CLASSES * FEAT) centers = (const float*)d_in[i];
        else                                        labels  = (const int*)d_in[i];
    }
    center_loss_kernel<<<NUM_BLOCKS, WARPS_PER_BLOCK * 32>>>(
        x, centers, labels, (float*)d_out);
}

// round 9
// speedup vs baseline: 1.0047x; 1.0047x over previous
#include <cuda_runtime.h>

#define BATCH 1024
#define FEAT 256
#define NUM_CLASSES 100000
#define CLAMP_MIN 1e-12f
#define CLAMP_MAX 1e12f
#define WARPS_PER_BLOCK 8
#define ROWS_PER_BLOCK WARPS_PER_BLOCK
#define NUM_BLOCKS (BATCH / ROWS_PER_BLOCK)   // 128

// Packed cross-block accumulator:
//   bits [52:64) = arrived-block count, bits [0:52) = sum in 2^-20 fixed point.
// Block partials are positive (clamped >= 1e-12) and < 2^19 * 8, so the fixed
// sum fits well under 2^52; count 128 < 2^12. One relaxed u64 RMW carries both
// the data and the "am I last?" ticket -> no fence, no second atomic, no final
// load. Quantization <= 2^-21 abs per block -> ~1e-10 relative on loss ~512.
#define COUNT_ONE (1ULL << 52)
#define SUM_MASK  (COUNT_ONE - 1ULL)
#define FIX_SCALE 1048576.0   // 2^20

__device__ unsigned long long g_pack = 0ULL;   // zero at load; reset by last block

__global__ __launch_bounds__(WARPS_PER_BLOCK * 32)
void center_loss_kernel(const float* __restrict__ x,
                        const float* __restrict__ centers,
                        const int* __restrict__ labels,   // JAX x64 disabled -> int32
                        float* __restrict__ out) {
    const int warp = threadIdx.x >> 5;
    const int lane = threadIdx.x & 31;
    const int row  = blockIdx.x * ROWS_PER_BLOCK + warp;

    // Label load starts the dependent gather chain immediately.
    int lbl = __ldg(&labels[row]);
    lbl = min(max(lbl, 0), NUM_CLASSES - 1);   // defensive, branch-free

    const float4* xr = reinterpret_cast<const float4*>(x + (size_t)row * FEAT);
    const float4* cr = reinterpret_cast<const float4*>(centers + (size_t)lbl * FEAT);

    // x loads are independent of the label -> in flight during the label wait.
    float4 a0 = xr[lane];
    float4 a1 = xr[lane + 32];
    float sx = a0.x*a0.x + a0.y*a0.y + a0.z*a0.z + a0.w*a0.w
             + a1.x*a1.x + a1.y*a1.y + a1.z*a1.z + a1.w*a1.w;

    float4 b0 = cr[lane];
    float4 b1 = cr[lane + 32];
    float sc  = b0.x*b0.x + b0.y*b0.y + b0.z*b0.z + b0.w*b0.w
              + b1.x*b1.x + b1.y*b1.y + b1.z*b1.z + b1.w*b1.w;
    float sxc = a0.x*b0.x + a0.y*b0.y + a0.z*b0.z + a0.w*b0.w
              + a1.x*b1.x + a1.y*b1.y + a1.z*b1.z + a1.w*b1.w;

    float p = sx + sc - 2.0f * sxc;

    // Warp reduction.
    #pragma unroll
    for (int off = 16; off > 0; off >>= 1)
        p += __shfl_xor_sync(0xFFFFFFFFu, p, off);

    __shared__ float bs[WARPS_PER_BLOCK];
    if (lane == 0)
        bs[warp] = fminf(fmaxf(p, CLAMP_MIN), CLAMP_MAX);   // clamp per row
    __syncthreads();

    // Warp 0: parallel reduce of the 8 warp partials, then one packed RMW.
    if (warp == 0 && lane < 8) {
        float s = bs[lane];
        #pragma unroll
        for (int off = 4; off > 0; off >>= 1)
            s += __shfl_xor_sync(0x000000FFu, s, off);

        if (lane == 0) {
            unsigned long long val =
                COUNT_ONE + (unsigned long long)__double2ll_rn((double)s * FIX_SCALE);
            unsigned long long old = atomicAdd(&g_pack, val);

            if ((old >> 52) == NUM_BLOCKS - 1) {
                // We are the last block; old+val holds the complete fixed sum.
                unsigned long long sum_fix = (old + val) & SUM_MASK;
                double tot = (double)sum_fix * (1.0 / FIX_SCALE);
                *out = (float)(tot * (1.0 / BATCH)
                             + (double)(NUM_CLASSES - 1) * 1e-12);
                g_pack = 0ULL;   // re-arm for next graph replay
            }
        }
    }
}

extern "C" void kernel_launch(void* const* d_in, const int* in_sizes, int n_in,
                              void* d_out, int out_size) {
    // Resolve inputs by element count:
    //   x: 1024*256 = 262144, centers: 100000*256 = 25600000, labels: 1024
    const float* x = nullptr;
    const float* centers = nullptr;
    const int*   labels = nullptr;
    for (int i = 0; i < n_in; i++) {
        if (in_sizes[i] == BATCH * FEAT)            x       = (const float*)d_in[i];
        else if (in_sizes[i] == NUM_CLASSES * FEAT) centers = (const float*)d_in[i];
        else                                        labels  = (const int*)d_in[i];
    }
    center_loss_kernel<<<NUM_BLOCKS, WARPS_PER_BLOCK * 32>>>(
        x, centers, labels, (float*)d_out);
}